// round 6
// baseline (speedup 1.0000x reference)
#include <cuda_runtime.h>
#include <cuda_bf16.h>
#include <math.h>
#include <float.h>
#include <stdint.h>

// Problem constants (match reference)
#define NN 100000
#define NE 1600000
#define NF 128
#define NL 7
#define SLOPE 0.02f

// ---------------- device scratch (static, no allocation) ----------------
// NOTE: zero-initialized at module load. g_counts is re-zeroed by fill_kernel
// and g_cursor by scan_kernel each call, so every call sees the same state.
__device__ int   g_counts[NN];
__device__ int   g_cursor[NN];
__device__ int   g_rowptr[NN + 1];
__device__ int   g_col[NE];
__device__ float g_h0[NN * NF];
__device__ float g_h1[NN * NF];
// pre-split weights: hi/lo bf16, layout [l][n][k] (same as input W)
__device__ __align__(16) uint16_t g_WlHi[NL * NF * NF];
__device__ __align__(16) uint16_t g_WlLo[NL * NF * NF];
__device__ __align__(16) uint16_t g_WrHi[NL * NF * NF];
__device__ __align__(16) uint16_t g_WrLo[NL * NF * NF];

// ---------------- CSR build (3 launches) + weight pre-split ----------------
__global__ void hist_kernel(const int* __restrict__ dst,
                            const float* __restrict__ Wl, const float* __restrict__ Wr) {
    int e = blockIdx.x * blockDim.x + threadIdx.x;
    if (e < NE) atomicAdd(&g_counts[dst[e]], 1);
    if (e < NL * NF * NF) {
        float a = Wl[e];
        __nv_bfloat16 h = __float2bfloat16(a);
        g_WlHi[e] = __bfloat16_as_ushort(h);
        g_WlLo[e] = __bfloat16_as_ushort(__float2bfloat16(a - __bfloat162float(h)));
        float b = Wr[e];
        __nv_bfloat16 hb = __float2bfloat16(b);
        g_WrHi[e] = __bfloat16_as_ushort(hb);
        g_WrLo[e] = __bfloat16_as_ushort(__float2bfloat16(b - __bfloat162float(hb)));
    }
}

// single-block exclusive scan over counts -> rowptr; also zeroes cursor
__global__ void scan_kernel() {
    __shared__ int s[1024];
    __shared__ int carry_s;
    int t = threadIdx.x;
    if (t == 0) carry_s = 0;
    __syncthreads();
    for (int base = 0; base < NN; base += 1024) {
        int c = carry_s;
        int i = base + t;
        int v = (i < NN) ? g_counts[i] : 0;
        if (i < NN) g_cursor[i] = 0;
        s[t] = v;
        __syncthreads();
#pragma unroll
        for (int d = 1; d < 1024; d <<= 1) {
            int add = (t >= d) ? s[t - d] : 0;
            __syncthreads();
            s[t] += add;
            __syncthreads();
        }
        int inc = s[t];
        if (i < NN) g_rowptr[i] = inc - v + c;     // exclusive
        if (t == 1023) carry_s = c + s[1023];
        __syncthreads();
    }
    if (t == 0) g_rowptr[NN] = NE;
}

// fill CSR; also re-zero counts for the next call
__global__ void fill_kernel(const int* __restrict__ src, const int* __restrict__ dst) {
    int e = blockIdx.x * blockDim.x + threadIdx.x;
    if (e < NN) g_counts[e] = 0;
    if (e < NE) {
        int d = dst[e];
        int off = atomicAdd(&g_cursor[d], 1);
        g_col[g_rowptr[d] + off] = src[e];
    }
}

// ---------------- helpers ----------------
__device__ __forceinline__ float4 fmax4(float4 a, float4 b) {
    a.x = fmaxf(a.x, b.x); a.y = fmaxf(a.y, b.y);
    a.z = fmaxf(a.z, b.z); a.w = fmaxf(a.w, b.w);
    return a;
}

__device__ __forceinline__ uint32_t smem_u32(const void* p) {
    uint32_t a;
    asm("{ .reg .u64 t; cvta.to.shared.u64 t, %1; cvt.u32.u64 %0, t; }" : "=r"(a) : "l"(p));
    return a;
}

__device__ __forceinline__ void ldm4(uint32_t* r, uint32_t addr) {
    asm volatile("ldmatrix.sync.aligned.m8n8.x4.shared.b16 {%0,%1,%2,%3}, [%4];"
                 : "=r"(r[0]), "=r"(r[1]), "=r"(r[2]), "=r"(r[3]) : "r"(addr));
}

__device__ __forceinline__ void mma_bf16(float* d, const uint32_t* a, uint32_t b0, uint32_t b1) {
    asm volatile(
        "mma.sync.aligned.m16n8k16.row.col.f32.bf16.bf16.f32 "
        "{%0,%1,%2,%3}, {%4,%5,%6,%7}, {%8,%9}, {%0,%1,%2,%3};"
        : "+f"(d[0]), "+f"(d[1]), "+f"(d[2]), "+f"(d[3])
        : "r"(a[0]), "r"(a[1]), "r"(a[2]), "r"(a[3]), "r"(b0), "r"(b1));
}

// ================= fused agg + bf16x3 dual GEMM, sync-free warps =================
// 1 CTA/SM (256 thr, 128 rows). All 4 weight planes staged once (139KB), then
// each warp runs independently: gather its 16 rows -> mma, load h rows -> mma.
#define A_STRIDE 272
#define PLANE    34816                 // 128 rows * 272B
#define SA_HI    0
#define SA_LO    PLANE
#define SB_BASE  (2 * PLANE)           // WlHi, WlLo, WrHi, WrLo planes follow
#define SM_TOT   (6 * PLANE)           // 208896 bytes

// split v into hi/lo bf16 and write 4 elements at (row, q)
__device__ __forceinline__ void write_split(char* smem, int row, int q, float4 v) {
    __nv_bfloat16 hx = __float2bfloat16(v.x);
    __nv_bfloat16 hy = __float2bfloat16(v.y);
    __nv_bfloat16 hz = __float2bfloat16(v.z);
    __nv_bfloat16 hw = __float2bfloat16(v.w);
    uint32_t hi01 = ((uint32_t)__bfloat16_as_ushort(hy) << 16) | __bfloat16_as_ushort(hx);
    uint32_t hi23 = ((uint32_t)__bfloat16_as_ushort(hw) << 16) | __bfloat16_as_ushort(hz);
    __nv_bfloat16 lx = __float2bfloat16(v.x - __bfloat162float(hx));
    __nv_bfloat16 ly = __float2bfloat16(v.y - __bfloat162float(hy));
    __nv_bfloat16 lz = __float2bfloat16(v.z - __bfloat162float(hz));
    __nv_bfloat16 lw = __float2bfloat16(v.w - __bfloat162float(hw));
    uint32_t lo01 = ((uint32_t)__bfloat16_as_ushort(ly) << 16) | __bfloat16_as_ushort(lx);
    uint32_t lo23 = ((uint32_t)__bfloat16_as_ushort(lw) << 16) | __bfloat16_as_ushort(lz);
    uint32_t off = (uint32_t)(row * A_STRIDE + q * 8);
    *(uint2*)(smem + SA_HI + off) = make_uint2(hi01, hi23);
    *(uint2*)(smem + SA_LO + off) = make_uint2(lo01, lo23);
}

// stage all 4 weight planes (WlHi, WlLo, WrHi, WrLo)
__device__ __forceinline__ void stage_all_w(char* smem,
    const uint16_t* __restrict__ WlHi, const uint16_t* __restrict__ WlLo,
    const uint16_t* __restrict__ WrHi, const uint16_t* __restrict__ WrLo, int tid)
{
    const uint16_t* srcs[4] = {WlHi, WlLo, WrHi, WrLo};
#pragma unroll
    for (int i = 0; i < 32; i++) {
        int idx = tid + i * 256;        // 0..8191 uint4s
        int plane = idx >> 11;          // 2048 uint4 per plane
        int rem = idx & 2047;
        int nl = rem >> 4;              // n-row 0..127
        int q  = rem & 15;              // uint4 within row
        const uint4* s = (const uint4*)(srcs[plane] + (size_t)nl * NF);
        *(uint4*)(smem + SB_BASE + plane * PLANE + nl * A_STRIDE + q * 16) = s[q];
    }
}

// gather (max-agg) 16 rows for this warp, MLP-8 inner loop
__device__ __forceinline__ void warp_gather(char* smem, const float* __restrict__ h,
                                            int rowBase, int M, int wid, int lane) {
    const float4* h4 = (const float4*)h;
#pragma unroll 1
    for (int j = 0; j < 16; j++) {
        int r = wid * 16 + j;
        int gm = rowBase + r;
        float4 m = make_float4(0.f, 0.f, 0.f, 0.f);
        if (gm < M) {
            int beg = g_rowptr[gm];
            int end = g_rowptr[gm + 1];
            if (beg < end) {
                float4 a = make_float4(-FLT_MAX, -FLT_MAX, -FLT_MAX, -FLT_MAX);
                int e = beg;
                for (; e + 8 <= end; e += 8) {
                    float4 v0 = h4[g_col[e]     * 32 + lane];
                    float4 v1 = h4[g_col[e + 1] * 32 + lane];
                    float4 v2 = h4[g_col[e + 2] * 32 + lane];
                    float4 v3 = h4[g_col[e + 3] * 32 + lane];
                    float4 v4 = h4[g_col[e + 4] * 32 + lane];
                    float4 v5 = h4[g_col[e + 5] * 32 + lane];
                    float4 v6 = h4[g_col[e + 6] * 32 + lane];
                    float4 v7 = h4[g_col[e + 7] * 32 + lane];
                    a = fmax4(a, fmax4(fmax4(fmax4(v0, v1), fmax4(v2, v3)),
                                       fmax4(fmax4(v4, v5), fmax4(v6, v7))));
                }
                for (; e < end; e++) a = fmax4(a, h4[g_col[e] * 32 + lane]);
                m = a;
            }
        }
        write_split(smem, r, lane, m);
    }
}

// load this warp's 16 h-rows (root branch)
__device__ __forceinline__ void warp_load_h(char* smem, const float* __restrict__ h,
                                            int rowBase, int M, int wid, int lane) {
    const float4* h4 = (const float4*)h;
#pragma unroll
    for (int j = 0; j < 16; j++) {
        int r = wid * 16 + j;
        int gm = rowBase + r;
        float4 v = make_float4(0.f, 0.f, 0.f, 0.f);
        if (gm < M) v = h4[gm * 32 + lane];
        write_split(smem, r, lane, v);
    }
}

// K=128 sweep over all 16 n8-tiles, 3-pass bf16 split; acc[16][4]
__device__ __forceinline__ void warp_mma(float acc[16][4],
                                         uint32_t aHiB, uint32_t aLoB,
                                         uint32_t bHiB, uint32_t bLoB) {
#pragma unroll
    for (int ks = 0; ks < 8; ks++) {
        uint32_t ko = ks * 32;   // 16 bf16 = 32 bytes per k-step
        uint32_t ah[4], al[4];
        ldm4(ah, aHiB + ko);
        ldm4(al, aLoB + ko);
#pragma unroll
        for (int p = 0; p < 8; p++) {
            uint32_t bh[4], blx[4];
            uint32_t po = (uint32_t)(p * 16 * A_STRIDE) + ko;
            ldm4(bh,  bHiB + po);
            ldm4(blx, bLoB + po);
            mma_bf16(acc[2 * p],     ah, bh[0],  bh[1]);
            mma_bf16(acc[2 * p],     ah, blx[0], blx[1]);
            mma_bf16(acc[2 * p],     al, bh[0],  bh[1]);
            mma_bf16(acc[2 * p + 1], ah, bh[2],  bh[3]);
            mma_bf16(acc[2 * p + 1], ah, blx[2], blx[3]);
            mma_bf16(acc[2 * p + 1], al, bh[2],  bh[3]);
        }
    }
}

__global__ __launch_bounds__(256, 1) void gemm_fused_kernel(
    const float* __restrict__ h,
    const uint16_t* __restrict__ WlHi, const uint16_t* __restrict__ WlLo,
    const uint16_t* __restrict__ WrHi, const uint16_t* __restrict__ WrLo,
    const float* __restrict__ bias, float* __restrict__ C, int M)
{
    extern __shared__ char smem[];
    uint32_t su = smem_u32(smem);
    int tid = threadIdx.x;
    int lane = tid & 31;
    int wid = tid >> 5;
    int rowBase = blockIdx.x * 128;

    // per-lane ldmatrix base addresses
    int lr = lane & 7, g = lane >> 3;
    uint32_t aOff = (uint32_t)((wid * 16 + lr + (g & 1) * 8) * A_STRIDE + (g >> 1) * 16);
    uint32_t bOff = (uint32_t)((lr + (g >> 1) * 8) * A_STRIDE + (g & 1) * 16);
    uint32_t aHiB = su + SA_HI + aOff;
    uint32_t aLoB = su + SA_LO + aOff;
    uint32_t wlHiB = su + SB_BASE + 0 * PLANE + bOff;
    uint32_t wlLoB = su + SB_BASE + 1 * PLANE + bOff;
    uint32_t wrHiB = su + SB_BASE + 2 * PLANE + bOff;
    uint32_t wrLoB = su + SB_BASE + 3 * PLANE + bOff;

    stage_all_w(smem, WlHi, WlLo, WrHi, WrLo, tid);
    __syncthreads();   // the only CTA-wide barrier

    float acc[16][4];
#pragma unroll
    for (int i = 0; i < 16; i++)
#pragma unroll
        for (int q = 0; q < 4; q++) acc[i][q] = 0.f;

    // warp-level phase stagger: even warps gather first, odd warps root-half first
    if ((wid & 1) == 0) {
        warp_gather(smem, h, rowBase, M, wid, lane);
        __syncwarp();
        warp_mma(acc, aHiB, aLoB, wlHiB, wlLoB);
        warp_load_h(smem, h, rowBase, M, wid, lane);
        __syncwarp();
        warp_mma(acc, aHiB, aLoB, wrHiB, wrLoB);
    } else {
        warp_load_h(smem, h, rowBase, M, wid, lane);
        __syncwarp();
        warp_mma(acc, aHiB, aLoB, wrHiB, wrLoB);
        warp_gather(smem, h, rowBase, M, wid, lane);
        __syncwarp();
        warp_mma(acc, aHiB, aLoB, wlHiB, wlLoB);
    }

    // ---- epilogue: bias + leaky, direct stores ----
    int r0 = rowBase + wid * 16 + (lane >> 2);
#pragma unroll
    for (int nt = 0; nt < 16; nt++) {
        int col = nt * 8 + 2 * (lane & 3);
        float b0 = bias[col], b1 = bias[col + 1];
        float v0 = acc[nt][0] + b0;
        float v1 = acc[nt][1] + b1;
        float v2 = acc[nt][2] + b0;
        float v3 = acc[nt][3] + b1;
        v0 = (v0 >= 0.f) ? v0 : SLOPE * v0;
        v1 = (v1 >= 0.f) ? v1 : SLOPE * v1;
        v2 = (v2 >= 0.f) ? v2 : SLOPE * v2;
        v3 = (v3 >= 0.f) ? v3 : SLOPE * v3;
        if (r0 < M)     *((float2*)&C[(size_t)r0 * NF + col])       = make_float2(v0, v1);
        if (r0 + 8 < M) *((float2*)&C[(size_t)(r0 + 8) * NF + col]) = make_float2(v2, v3);
    }
}

// ---------------- fused final layer: gather max + 3-dim output ----------------
__global__ __launch_bounds__(256) void aggout_kernel(
    const float* __restrict__ h,
    const float* __restrict__ Wl, const float* __restrict__ bl,
    const float* __restrict__ Wr, float* __restrict__ out)
{
    int warp = (blockIdx.x * blockDim.x + threadIdx.x) >> 5;
    int lane = threadIdx.x & 31;
    if (warp >= NN) return;
    const float4* h4 = (const float4*)h;
    int beg = g_rowptr[warp];
    int end = g_rowptr[warp + 1];
    float4 m = make_float4(-FLT_MAX, -FLT_MAX, -FLT_MAX, -FLT_MAX);
    int e = beg;
    for (; e + 8 <= end; e += 8) {
        float4 v0 = h4[g_col[e]     * 32 + lane];
        float4 v1 = h4[g_col[e + 1] * 32 + lane];
        float4 v2 = h4[g_col[e + 2] * 32 + lane];
        float4 v3 = h4[g_col[e + 3] * 32 + lane];
        float4 v4 = h4[g_col[e + 4] * 32 + lane];
        float4 v5 = h4[g_col[e + 5] * 32 + lane];
        float4 v6 = h4[g_col[e + 6] * 32 + lane];
        float4 v7 = h4[g_col[e + 7] * 32 + lane];
        m = fmax4(m, fmax4(fmax4(fmax4(v0, v1), fmax4(v2, v3)),
                           fmax4(fmax4(v4, v5), fmax4(v6, v7))));
    }
    for (; e < end; e++) m = fmax4(m, h4[g_col[e] * 32 + lane]);
    if (beg == end) m = make_float4(0.f, 0.f, 0.f, 0.f);

    float4 hv = h4[warp * 32 + lane];
#pragma unroll
    for (int o = 0; o < 3; o++) {
        float4 wl = ((const float4*)Wl)[o * 32 + lane];
        float4 wr = ((const float4*)Wr)[o * 32 + lane];
        float s = m.x * wl.x + m.y * wl.y + m.z * wl.z + m.w * wl.w
                + hv.x * wr.x + hv.y * wr.y + hv.z * wr.z + hv.w * wr.w;
#pragma unroll
        for (int off = 16; off; off >>= 1)
            s += __shfl_xor_sync(0xffffffff, s, off);
        if (lane == 0) out[warp * 3 + o] = tanhf(s + bl[o]) * 0.5f;
    }
}

// ---------------- host launcher ----------------
extern "C" void kernel_launch(void* const* d_in, const int* in_sizes, int n_in,
                              void* d_out, int out_size)
{
    const float* x      = (const float*)d_in[0];
    const int*   ei     = (const int*)d_in[1];
    const float* Wl     = (const float*)d_in[2];
    const float* bl     = (const float*)d_in[3];
    const float* Wr     = (const float*)d_in[4];
    const float* Wl_out = (const float*)d_in[5];
    const float* bl_out = (const float*)d_in[6];
    const float* Wr_out = (const float*)d_in[7];
    float* out = (float*)d_out;

    const int* src = ei;
    const int* dst = ei + NE;

    void *pH0, *pH1, *pWlHi, *pWlLo, *pWrHi, *pWrLo;
    cudaGetSymbolAddress(&pH0, g_h0);
    cudaGetSymbolAddress(&pH1, g_h1);
    cudaGetSymbolAddress(&pWlHi, g_WlHi);
    cudaGetSymbolAddress(&pWlLo, g_WlLo);
    cudaGetSymbolAddress(&pWrHi, g_WrHi);
    cudaGetSymbolAddress(&pWrLo, g_WrLo);
    float* h0  = (float*)pH0;
    float* h1  = (float*)pH1;
    uint16_t* wlHi = (uint16_t*)pWlHi;
    uint16_t* wlLo = (uint16_t*)pWlLo;
    uint16_t* wrHi = (uint16_t*)pWrHi;
    uint16_t* wrLo = (uint16_t*)pWrLo;

    cudaFuncSetAttribute(gemm_fused_kernel, cudaFuncAttributeMaxDynamicSharedMemorySize, SM_TOT);

    // CSR build (3 launches) -> launch #4 is the layer-0 GEMM (profiled by ncu)
    hist_kernel<<<(NE + 255) / 256, 256>>>(dst, Wl, Wr);
    scan_kernel<<<1, 1024>>>();
    fill_kernel<<<(NE + 255) / 256, 256>>>(src, dst);

    const int AGG_BLOCKS  = (NN + 7) / 8;
    const int GEMM_BLOCKS = (NN + 127) / 128;

    const float* cur = x;
    for (int i = 0; i < NL; i++) {
        float* nxt = (i & 1) ? h1 : h0;
        gemm_fused_kernel<<<GEMM_BLOCKS, 256, SM_TOT>>>(
            cur,
            wlHi + (size_t)i * NF * NF, wlLo + (size_t)i * NF * NF,
            wrHi + (size_t)i * NF * NF, wrLo + (size_t)i * NF * NF,
            bl + i * NF, nxt, NN);
        cur = nxt;
    }

    // fused final aggregation + output conv
    aggout_kernel<<<AGG_BLOCKS, 256>>>(cur, Wl_out, bl_out, Wr_out, out);
}

// round 7
// speedup vs baseline: 1.6647x; 1.6647x over previous
#include <cuda_runtime.h>
#include <cuda_bf16.h>
#include <math.h>
#include <float.h>
#include <stdint.h>

// Problem constants (match reference)
#define NN 100000
#define NE 1600000
#define NF 128
#define NL 7
#define SLOPE 0.02f

// ---------------- device scratch (static, no allocation) ----------------
// zero-initialized at load; g_counts re-zeroed by fill_kernel, g_cursor by
// scan_kernel each call -> deterministic across calls.
__device__ int   g_counts[NN];
__device__ int   g_cursor[NN];
__device__ int   g_rowptr[NN + 1];
__device__ int   g_col[NE];
__device__ float g_h0[NN * NF];
__device__ float g_h1[NN * NF];
__device__ float g_agg[NN * NF];
// pre-split weights: hi/lo bf16, layout [l][n][k] (same as input W)
__device__ __align__(16) uint16_t g_WlHi[NL * NF * NF];
__device__ __align__(16) uint16_t g_WlLo[NL * NF * NF];
__device__ __align__(16) uint16_t g_WrHi[NL * NF * NF];
__device__ __align__(16) uint16_t g_WrLo[NL * NF * NF];

// ---------------- CSR build (3 launches) + weight pre-split ----------------
__global__ void hist_kernel(const int* __restrict__ dst,
                            const float* __restrict__ Wl, const float* __restrict__ Wr) {
    int e = blockIdx.x * blockDim.x + threadIdx.x;
    if (e < NE) atomicAdd(&g_counts[dst[e]], 1);
    if (e < NL * NF * NF) {
        float a = Wl[e];
        __nv_bfloat16 h = __float2bfloat16(a);
        g_WlHi[e] = __bfloat16_as_ushort(h);
        g_WlLo[e] = __bfloat16_as_ushort(__float2bfloat16(a - __bfloat162float(h)));
        float b = Wr[e];
        __nv_bfloat16 hb = __float2bfloat16(b);
        g_WrHi[e] = __bfloat16_as_ushort(hb);
        g_WrLo[e] = __bfloat16_as_ushort(__float2bfloat16(b - __bfloat162float(hb)));
    }
}

// single-block exclusive scan over counts -> rowptr; also zeroes cursor
__global__ void scan_kernel() {
    __shared__ int s[1024];
    __shared__ int carry_s;
    int t = threadIdx.x;
    if (t == 0) carry_s = 0;
    __syncthreads();
    for (int base = 0; base < NN; base += 1024) {
        int c = carry_s;
        int i = base + t;
        int v = (i < NN) ? g_counts[i] : 0;
        if (i < NN) g_cursor[i] = 0;
        s[t] = v;
        __syncthreads();
#pragma unroll
        for (int d = 1; d < 1024; d <<= 1) {
            int add = (t >= d) ? s[t - d] : 0;
            __syncthreads();
            s[t] += add;
            __syncthreads();
        }
        int inc = s[t];
        if (i < NN) g_rowptr[i] = inc - v + c;     // exclusive
        if (t == 1023) carry_s = c + s[1023];
        __syncthreads();
    }
    if (t == 0) g_rowptr[NN] = NE;
}

// fill CSR; also re-zero counts for the next call
__global__ void fill_kernel(const int* __restrict__ src, const int* __restrict__ dst) {
    int e = blockIdx.x * blockDim.x + threadIdx.x;
    if (e < NN) g_counts[e] = 0;
    if (e < NE) {
        int d = dst[e];
        int off = atomicAdd(&g_cursor[d], 1);
        g_col[g_rowptr[d] + off] = src[e];
    }
}

// ---------------- helpers ----------------
__device__ __forceinline__ float4 fmax4(float4 a, float4 b) {
    a.x = fmaxf(a.x, b.x); a.y = fmaxf(a.y, b.y);
    a.z = fmaxf(a.z, b.z); a.w = fmaxf(a.w, b.w);
    return a;
}

__device__ __forceinline__ uint32_t smem_u32(const void* p) {
    uint32_t a;
    asm("{ .reg .u64 t; cvta.to.shared.u64 t, %1; cvt.u32.u64 %0, t; }" : "=r"(a) : "l"(p));
    return a;
}

__device__ __forceinline__ void ldm4(uint32_t* r, uint32_t addr) {
    asm volatile("ldmatrix.sync.aligned.m8n8.x4.shared.b16 {%0,%1,%2,%3}, [%4];"
                 : "=r"(r[0]), "=r"(r[1]), "=r"(r[2]), "=r"(r[3]) : "r"(addr));
}

__device__ __forceinline__ void mma_bf16(float* d, const uint32_t* a, uint32_t b0, uint32_t b1) {
    asm volatile(
        "mma.sync.aligned.m16n8k16.row.col.f32.bf16.bf16.f32 "
        "{%0,%1,%2,%3}, {%4,%5,%6,%7}, {%8,%9}, {%0,%1,%2,%3};"
        : "+f"(d[0]), "+f"(d[1]), "+f"(d[2]), "+f"(d[3])
        : "r"(a[0]), "r"(a[1]), "r"(a[2]), "r"(a[3]), "r"(b0), "r"(b1));
}

// ---------------- standalone max aggregation: warp per node, MLP-8 ----------------
__global__ __launch_bounds__(256) void agg_kernel(const float* __restrict__ h,
                                                  float* __restrict__ agg) {
    int warp = (blockIdx.x * blockDim.x + threadIdx.x) >> 5;
    int lane = threadIdx.x & 31;
    if (warp >= NN) return;
    int beg = g_rowptr[warp];
    int end = g_rowptr[warp + 1];
    const float4* h4 = (const float4*)h;
    float4 m = make_float4(-FLT_MAX, -FLT_MAX, -FLT_MAX, -FLT_MAX);
    int e = beg;
    for (; e + 8 <= end; e += 8) {
        float4 v0 = h4[g_col[e]     * 32 + lane];
        float4 v1 = h4[g_col[e + 1] * 32 + lane];
        float4 v2 = h4[g_col[e + 2] * 32 + lane];
        float4 v3 = h4[g_col[e + 3] * 32 + lane];
        float4 v4 = h4[g_col[e + 4] * 32 + lane];
        float4 v5 = h4[g_col[e + 5] * 32 + lane];
        float4 v6 = h4[g_col[e + 6] * 32 + lane];
        float4 v7 = h4[g_col[e + 7] * 32 + lane];
        m = fmax4(m, fmax4(fmax4(fmax4(v0, v1), fmax4(v2, v3)),
                           fmax4(fmax4(v4, v5), fmax4(v6, v7))));
    }
    for (; e < end; e++) m = fmax4(m, h4[g_col[e] * 32 + lane]);
    if (beg == end) m = make_float4(0.f, 0.f, 0.f, 0.f);
    ((float4*)agg)[warp * 32 + lane] = m;
}

// ================= bf16x3 tensor-core dual GEMM (streaming A) =================
// C[M,128] = A0[M,128]@Wl^T + A1[M,128]@Wr^T + bias, then leaky.
#define A_STRIDE 272
#define SA_HI 0
#define SA_LO 34816
#define SB_HI 69632
#define SB_LO 87040
#define SM_TOT 104448

// split v into hi/lo bf16 and write 4 elements at (row, q)
__device__ __forceinline__ void write_split(char* smem, int row, int q, float4 v) {
    __nv_bfloat16 hx = __float2bfloat16(v.x);
    __nv_bfloat16 hy = __float2bfloat16(v.y);
    __nv_bfloat16 hz = __float2bfloat16(v.z);
    __nv_bfloat16 hw = __float2bfloat16(v.w);
    uint32_t hi01 = ((uint32_t)__bfloat16_as_ushort(hy) << 16) | __bfloat16_as_ushort(hx);
    uint32_t hi23 = ((uint32_t)__bfloat16_as_ushort(hw) << 16) | __bfloat16_as_ushort(hz);
    __nv_bfloat16 lx = __float2bfloat16(v.x - __bfloat162float(hx));
    __nv_bfloat16 ly = __float2bfloat16(v.y - __bfloat162float(hy));
    __nv_bfloat16 lz = __float2bfloat16(v.z - __bfloat162float(hz));
    __nv_bfloat16 lw = __float2bfloat16(v.w - __bfloat162float(hw));
    uint32_t lo01 = ((uint32_t)__bfloat16_as_ushort(ly) << 16) | __bfloat16_as_ushort(lx);
    uint32_t lo23 = ((uint32_t)__bfloat16_as_ushort(lw) << 16) | __bfloat16_as_ushort(lz);
    uint32_t off = (uint32_t)(row * A_STRIDE + q * 8);
    *(uint2*)(smem + SA_HI + off) = make_uint2(hi01, hi23);
    *(uint2*)(smem + SA_LO + off) = make_uint2(lo01, lo23);
}

// stage one 64-n chunk of pre-split weights into sB
__device__ __forceinline__ void stage_w(char* smem, const uint16_t* __restrict__ WHi,
                                        const uint16_t* __restrict__ WLo, int nbase, int tid) {
#pragma unroll
    for (int i = 0; i < 4; i++) {
        int idx = tid + i * 256;         // 0..1023
        int nl = idx >> 4;               // 0..63
        int q  = idx & 15;               // uint4 within 128-k row
        const uint4* sh = (const uint4*)(WHi + (size_t)(nbase + nl) * NF);
        const uint4* sl = (const uint4*)(WLo + (size_t)(nbase + nl) * NF);
        *(uint4*)(smem + SB_HI + nl * A_STRIDE + q * 16) = sh[q];
        *(uint4*)(smem + SB_LO + nl * A_STRIDE + q * 16) = sl[q];
    }
}

// stage 128 A-rows (fp32 gmem -> split bf16 smem), linear coalesced
__device__ __forceinline__ void stage_A(char* smem, const float* __restrict__ src,
                                        int rowBase, int M, int tid) {
    const float4* s4 = (const float4*)src;
#pragma unroll
    for (int i = 0; i < 16; i++) {
        int idx = tid + i * 256;
        int row = idx >> 5;
        int q   = idx & 31;
        int gm  = rowBase + row;
        float4 v = make_float4(0.f, 0.f, 0.f, 0.f);
        if (gm < M) v = s4[gm * 32 + q];
        write_split(smem, row, q, v);
    }
}

// one K=128 sweep for one 64-n chunk: 3-pass bf16 split
__device__ __forceinline__ void mma_block(float acc[8][4],
                                          uint32_t aHiB, uint32_t aLoB,
                                          uint32_t bHiB, uint32_t bLoB) {
#pragma unroll
    for (int ks = 0; ks < 8; ks++) {
        uint32_t ko = ks * 32;   // 16 bf16 = 32 bytes per k-step
        uint32_t ah[4], al[4];
        ldm4(ah, aHiB + ko);
        ldm4(al, aLoB + ko);
#pragma unroll
        for (int p = 0; p < 4; p++) {
            uint32_t bh[4], blx[4];
            uint32_t po = (uint32_t)(p * 16 * A_STRIDE) + ko;
            ldm4(bh,  bHiB + po);
            ldm4(blx, bLoB + po);
            mma_bf16(acc[2 * p],     ah, bh[0],  bh[1]);
            mma_bf16(acc[2 * p],     ah, blx[0], blx[1]);
            mma_bf16(acc[2 * p],     al, bh[0],  bh[1]);
            mma_bf16(acc[2 * p + 1], ah, bh[2],  bh[3]);
            mma_bf16(acc[2 * p + 1], ah, blx[2], blx[3]);
            mma_bf16(acc[2 * p + 1], al, bh[2],  bh[3]);
        }
    }
}

// one accumulation half: stage A + both B chunks, mma both
__device__ __forceinline__ void run_half(
    char* smem, const float* __restrict__ src,
    const uint16_t* __restrict__ WHi, const uint16_t* __restrict__ WLo,
    int rowBase, int M, int tid,
    float acc0[8][4], float acc1[8][4],
    uint32_t aHiB, uint32_t aLoB, uint32_t bHiB, uint32_t bLoB)
{
    stage_w(smem, WHi, WLo, 0, tid);
    stage_A(smem, src, rowBase, M, tid);
    __syncthreads();
    mma_block(acc0, aHiB, aLoB, bHiB, bLoB);
    __syncthreads();
    stage_w(smem, WHi, WLo, 64, tid);
    __syncthreads();
    mma_block(acc1, aHiB, aLoB, bHiB, bLoB);
    __syncthreads();
}

__global__ __launch_bounds__(256, 2) void gemm_kernel(
    const float* __restrict__ agg, const float* __restrict__ h,
    const uint16_t* __restrict__ WlHi, const uint16_t* __restrict__ WlLo,
    const uint16_t* __restrict__ WrHi, const uint16_t* __restrict__ WrLo,
    const float* __restrict__ bias, float* __restrict__ C, int M)
{
    extern __shared__ char smem[];
    uint32_t su = smem_u32(smem);
    int tid = threadIdx.x;
    int lane = tid & 31;
    int wid = tid >> 5;
    int rowBase = blockIdx.x * 128;

    // per-lane ldmatrix base addresses
    int lr = lane & 7, g = lane >> 3;
    uint32_t aOff = (uint32_t)((wid * 16 + lr + (g & 1) * 8) * A_STRIDE + (g >> 1) * 16);
    uint32_t bOff = (uint32_t)((lr + (g >> 1) * 8) * A_STRIDE + (g & 1) * 16);
    uint32_t aHiB = su + SA_HI + aOff, aLoB = su + SA_LO + aOff;
    uint32_t bHiB = su + SB_HI + bOff, bLoB = su + SB_LO + bOff;

    float acc0[8][4], acc1[8][4];
#pragma unroll
    for (int i = 0; i < 8; i++)
#pragma unroll
        for (int q = 0; q < 4; q++) { acc0[i][q] = 0.f; acc1[i][q] = 0.f; }

    run_half(smem, agg, WlHi, WlLo, rowBase, M, tid, acc0, acc1, aHiB, aLoB, bHiB, bLoB);
    run_half(smem, h,   WrHi, WrLo, rowBase, M, tid, acc0, acc1, aHiB, aLoB, bHiB, bLoB);

    // ---- epilogue: bias + leaky, direct stores ----
    int r0 = rowBase + wid * 16 + (lane >> 2);
#pragma unroll
    for (int half = 0; half < 2; half++) {
        float (*A)[4] = half ? acc1 : acc0;
        int cbase = half * 64;
#pragma unroll
        for (int nt = 0; nt < 8; nt++) {
            int col = cbase + nt * 8 + 2 * (lane & 3);
            float b0 = bias[col], b1 = bias[col + 1];
            float v0 = A[nt][0] + b0;
            float v1 = A[nt][1] + b1;
            float v2 = A[nt][2] + b0;
            float v3 = A[nt][3] + b1;
            v0 = (v0 >= 0.f) ? v0 : SLOPE * v0;
            v1 = (v1 >= 0.f) ? v1 : SLOPE * v1;
            v2 = (v2 >= 0.f) ? v2 : SLOPE * v2;
            v3 = (v3 >= 0.f) ? v3 : SLOPE * v3;
            if (r0 < M)     *((float2*)&C[(size_t)r0 * NF + col])       = make_float2(v0, v1);
            if (r0 + 8 < M) *((float2*)&C[(size_t)(r0 + 8) * NF + col]) = make_float2(v2, v3);
        }
    }
}

// ---------------- fused final layer: gather max + 3-dim output ----------------
__global__ __launch_bounds__(256) void aggout_kernel(
    const float* __restrict__ h,
    const float* __restrict__ Wl, const float* __restrict__ bl,
    const float* __restrict__ Wr, float* __restrict__ out)
{
    int warp = (blockIdx.x * blockDim.x + threadIdx.x) >> 5;
    int lane = threadIdx.x & 31;
    if (warp >= NN) return;
    const float4* h4 = (const float4*)h;
    int beg = g_rowptr[warp];
    int end = g_rowptr[warp + 1];
    float4 m = make_float4(-FLT_MAX, -FLT_MAX, -FLT_MAX, -FLT_MAX);
    int e = beg;
    for (; e + 8 <= end; e += 8) {
        float4 v0 = h4[g_col[e]     * 32 + lane];
        float4 v1 = h4[g_col[e + 1] * 32 + lane];
        float4 v2 = h4[g_col[e + 2] * 32 + lane];
        float4 v3 = h4[g_col[e + 3] * 32 + lane];
        float4 v4 = h4[g_col[e + 4] * 32 + lane];
        float4 v5 = h4[g_col[e + 5] * 32 + lane];
        float4 v6 = h4[g_col[e + 6] * 32 + lane];
        float4 v7 = h4[g_col[e + 7] * 32 + lane];
        m = fmax4(m, fmax4(fmax4(fmax4(v0, v1), fmax4(v2, v3)),
                           fmax4(fmax4(v4, v5), fmax4(v6, v7))));
    }
    for (; e < end; e++) m = fmax4(m, h4[g_col[e] * 32 + lane]);
    if (beg == end) m = make_float4(0.f, 0.f, 0.f, 0.f);

    float4 hv = h4[warp * 32 + lane];
#pragma unroll
    for (int o = 0; o < 3; o++) {
        float4 wl = ((const float4*)Wl)[o * 32 + lane];
        float4 wr = ((const float4*)Wr)[o * 32 + lane];
        float s = m.x * wl.x + m.y * wl.y + m.z * wl.z + m.w * wl.w
                + hv.x * wr.x + hv.y * wr.y + hv.z * wr.z + hv.w * wr.w;
#pragma unroll
        for (int off = 16; off; off >>= 1)
            s += __shfl_xor_sync(0xffffffff, s, off);
        if (lane == 0) out[warp * 3 + o] = tanhf(s + bl[o]) * 0.5f;
    }
}

// ---------------- host launcher ----------------
extern "C" void kernel_launch(void* const* d_in, const int* in_sizes, int n_in,
                              void* d_out, int out_size)
{
    const float* x      = (const float*)d_in[0];
    const int*   ei     = (const int*)d_in[1];
    const float* Wl     = (const float*)d_in[2];
    const float* bl     = (const float*)d_in[3];
    const float* Wr     = (const float*)d_in[4];
    const float* Wl_out = (const float*)d_in[5];
    const float* bl_out = (const float*)d_in[6];
    const float* Wr_out = (const float*)d_in[7];
    float* out = (float*)d_out;

    const int* src = ei;
    const int* dst = ei + NE;

    void *pH0, *pH1, *pAgg, *pWlHi, *pWlLo, *pWrHi, *pWrLo;
    cudaGetSymbolAddress(&pH0, g_h0);
    cudaGetSymbolAddress(&pH1, g_h1);
    cudaGetSymbolAddress(&pAgg, g_agg);
    cudaGetSymbolAddress(&pWlHi, g_WlHi);
    cudaGetSymbolAddress(&pWlLo, g_WlLo);
    cudaGetSymbolAddress(&pWrHi, g_WrHi);
    cudaGetSymbolAddress(&pWrLo, g_WrLo);
    float* h0  = (float*)pH0;
    float* h1  = (float*)pH1;
    float* agg = (float*)pAgg;
    uint16_t* wlHi = (uint16_t*)pWlHi;
    uint16_t* wlLo = (uint16_t*)pWlLo;
    uint16_t* wrHi = (uint16_t*)pWrHi;
    uint16_t* wrLo = (uint16_t*)pWrLo;

    cudaFuncSetAttribute(gemm_kernel, cudaFuncAttributeMaxDynamicSharedMemorySize, SM_TOT);

    // CSR build (3 launches) -> launch #4 is agg layer 0 (profiled by ncu)
    hist_kernel<<<(NE + 255) / 256, 256>>>(dst, Wl, Wr);
    scan_kernel<<<1, 1024>>>();
    fill_kernel<<<(NE + 255) / 256, 256>>>(src, dst);

    const int AGG_BLOCKS  = (NN + 7) / 8;
    const int GEMM_BLOCKS = (NN + 127) / 128;

    const float* cur = x;
    for (int i = 0; i < NL; i++) {
        agg_kernel<<<AGG_BLOCKS, 256>>>(cur, agg);
        float* nxt = (i & 1) ? h1 : h0;
        gemm_kernel<<<GEMM_BLOCKS, 256, SM_TOT>>>(
            agg, cur,
            wlHi + (size_t)i * NF * NF, wlLo + (size_t)i * NF * NF,
            wrHi + (size_t)i * NF * NF, wrLo + (size_t)i * NF * NF,
            bl + i * NF, nxt, NN);
        cur = nxt;
    }

    // fused final aggregation + output conv
    aggout_kernel<<<AGG_BLOCKS, 256>>>(cur, Wl_out, bl_out, Wr_out, out);
}